// round 1
// baseline (speedup 1.0000x reference)
#include <cuda_runtime.h>
#include <cstdint>

#define S_LEN 2048
#define NHEAD 16
#define HDIM  64
#define NREL  65
#define NBH   32        // B * H
#define NM    4096      // B * S
#define ND    1024      // hidden

// ---------------- scratch (static device allocations only) ----------------
__device__ float g_Q[NBH * S_LEN * HDIM];
__device__ float g_K[NBH * S_LEN * HDIM];
__device__ float g_V[NBH * S_LEN * HDIM];
__device__ float g_O[NBH * S_LEN * HDIM];
__device__ float g_QE[NBH * S_LEN * NREL];

// ---------------- helpers ----------------
__device__ __forceinline__ uint32_t f2tf(float f) {
    uint32_t r;
    asm("cvt.rna.tf32.f32 %0, %1;" : "=r"(r) : "f"(f));
    return r;
}

__device__ __forceinline__ void mma8(float* c, const uint32_t* a, const uint32_t* b) {
    asm volatile(
        "mma.sync.aligned.m16n8k8.row.col.f32.tf32.tf32.f32 "
        "{%0,%1,%2,%3}, {%4,%5,%6,%7}, {%8,%9}, {%0,%1,%2,%3};\n"
        : "+f"(c[0]), "+f"(c[1]), "+f"(c[2]), "+f"(c[3])
        : "r"(a[0]), "r"(a[1]), "r"(a[2]), "r"(a[3]), "r"(b[0]), "r"(b[1]));
}

// split x into tf32 hi + tf32 lo (3xTF32 trick; residual ~2^-22)
__device__ __forceinline__ void tsplit(float v, uint32_t& hi, uint32_t& lo) {
    hi = f2tf(v);
    lo = f2tf(v - __uint_as_float(hi));
}

// =====================================================================
// GEMM: C[m,n] = sum_k A[m,k] * W[n,k]   (A: 4096x1024, W: 1024x1024)
// MODE 0/1/2: A = x, write head layout into g_Q/g_K/g_V
// MODE 3:     A = g_O (head layout gather), write d_out row-major + bias
// 3xTF32: smem holds raw fp32; hi/lo computed at fragment load.
// =====================================================================
#define GBM 128
#define GBN 128
#define GKS 20   // smem row stride (floats): conflict-free for frag reads

template <int MODE>
__global__ __launch_bounds__(256) void gemm_k(const float* __restrict__ A,
                                              const float* __restrict__ W,
                                              const float* __restrict__ bias,
                                              float* __restrict__ Cout) {
    __shared__ __align__(16) float As[2][GBM * GKS];
    __shared__ __align__(16) float Bs[2][GBN * GKS];

    const int tid = threadIdx.x, lane = tid & 31, wrp = tid >> 5;
    const int wm = (wrp >> 2) * 64, wn = (wrp & 3) * 32;
    const int m0 = blockIdx.y * GBM, n0 = blockIdx.x * GBN;
    const int r = lane >> 2, cc = lane & 3;

    const float* Ag = (MODE == 3) ? (const float*)g_O : A;

    float acc[4][4][4];
#pragma unroll
    for (int i = 0; i < 4; i++)
#pragma unroll
        for (int j = 0; j < 4; j++)
#pragma unroll
            for (int e = 0; e < 4; e++) acc[i][j][e] = 0.f;

    float4 ra[2], rb[2];

    auto ldA = [&](int kc) {
#pragma unroll
        for (int i = 0; i < 2; i++) {
            int idx = tid + (i << 8);
            int row = idx >> 2, kf = (idx & 3) << 2;
            int m = m0 + row, k = kc + kf;
            const float* p;
            if (MODE == 3) {
                int b = m >> 11, s = m & 2047, h = k >> 6, d = k & 63;
                p = Ag + ((((size_t)(b * NHEAD + h)) * S_LEN + s) * HDIM + d);
            } else {
                p = Ag + (size_t)m * ND + k;
            }
            ra[i] = *(const float4*)p;
        }
    };
    auto ldB = [&](int kc) {
#pragma unroll
        for (int i = 0; i < 2; i++) {
            int idx = tid + (i << 8);
            int row = idx >> 2, kf = (idx & 3) << 2;
            rb[i] = *(const float4*)(W + (size_t)(n0 + row) * ND + kc + kf);
        }
    };
    auto sts = [&](int buf) {
#pragma unroll
        for (int i = 0; i < 2; i++) {
            int idx = tid + (i << 8);
            int row = idx >> 2, kf = (idx & 3) << 2;
            *(float4*)&As[buf][row * GKS + kf] = ra[i];
            *(float4*)&Bs[buf][row * GKS + kf] = rb[i];
        }
    };

    ldA(0); ldB(0); sts(0);
    __syncthreads();

    for (int c = 0; c < 64; c++) {
        int buf = c & 1;
        if (c < 63) { ldA((c + 1) << 4); ldB((c + 1) << 4); }

#pragma unroll
        for (int ks = 0; ks < 2; ks++) {
            uint32_t ahi[4][4], alo[4][4], bhi[4][2], blo[4][2];
#pragma unroll
            for (int mi = 0; mi < 4; mi++) {
                int rr = wm + mi * 16 + r;
                int kk = ks * 8 + cc;
                float v0 = As[buf][rr * GKS + kk];
                float v1 = As[buf][(rr + 8) * GKS + kk];
                float v2 = As[buf][rr * GKS + kk + 4];
                float v3 = As[buf][(rr + 8) * GKS + kk + 4];
                tsplit(v0, ahi[mi][0], alo[mi][0]);
                tsplit(v1, ahi[mi][1], alo[mi][1]);
                tsplit(v2, ahi[mi][2], alo[mi][2]);
                tsplit(v3, ahi[mi][3], alo[mi][3]);
            }
#pragma unroll
            for (int ni = 0; ni < 4; ni++) {
                int rr = wn + ni * 8 + r;
                int kk = ks * 8 + cc;
                float v0 = Bs[buf][rr * GKS + kk];
                float v1 = Bs[buf][rr * GKS + kk + 4];
                tsplit(v0, bhi[ni][0], blo[ni][0]);
                tsplit(v1, bhi[ni][1], blo[ni][1]);
            }
#pragma unroll
            for (int mi = 0; mi < 4; mi++)
#pragma unroll
                for (int ni = 0; ni < 4; ni++) {
                    mma8(acc[mi][ni], ahi[mi], bhi[ni]);
                    mma8(acc[mi][ni], ahi[mi], blo[ni]);
                    mma8(acc[mi][ni], alo[mi], bhi[ni]);
                }
        }
        if (c < 63) { sts(buf ^ 1); __syncthreads(); }
    }

    // epilogue
#pragma unroll
    for (int mi = 0; mi < 4; mi++)
#pragma unroll
        for (int ni = 0; ni < 4; ni++)
#pragma unroll
            for (int half = 0; half < 2; half++) {
                int row = m0 + wm + mi * 16 + r + half * 8;
                int col = n0 + wn + ni * 8 + cc * 2;
                float v0 = acc[mi][ni][half * 2];
                float v1 = acc[mi][ni][half * 2 + 1];
                if (MODE == 3) {
                    v0 += bias[col];
                    v1 += bias[col + 1];
                    *(float2*)(Cout + (size_t)row * ND + col) = make_float2(v0, v1);
                } else {
                    float* dst = (MODE == 0) ? g_Q : (MODE == 1) ? g_K : g_V;
                    int b = row >> 11, s = row & 2047, h = col >> 6, d = col & 63;
                    *(float2*)(dst + (((size_t)(b * NHEAD + h)) * S_LEN + s) * HDIM + d) =
                        make_float2(v0, v1);
                }
            }
}

// =====================================================================
// qe[bh, q, v] = sum_d Q[bh, q, d] * rel[v, d]      (tiny, fp32 exact)
// 256 thr = 8 warps, warp handles one q row; lane covers v, v+32, (v=64)
// =====================================================================
__global__ void qe_k(const float* __restrict__ rel) {
    __shared__ float rs[NREL * 65];
    const int tid = threadIdx.x, lane = tid & 31, wp = tid >> 5;
    for (int i = tid; i < NREL * 64; i += 256) {
        int v = i >> 6, d = i & 63;
        rs[v * 65 + d] = rel[i];
    }
    __syncthreads();

    int q = blockIdx.x * 8 + wp;  // 0 .. 65535
    const float* qrow = g_Q + (size_t)q * HDIM;
    float a0 = 0.f, a1 = 0.f, a2 = 0.f;
#pragma unroll 8
    for (int d = 0; d < 64; d++) {
        float qd = qrow[d];
        a0 += qd * rs[lane * 65 + d];
        a1 += qd * rs[(lane + 32) * 65 + d];
        if (lane == 0) a2 += qd * rs[64 * 65 + d];
    }
    float* out = g_QE + (size_t)q * NREL;
    out[lane] = a0;
    out[lane + 32] = a1;
    if (lane == 0) out[64] = a2;
}

// =====================================================================
// Flash attention. CTA = (64 queries) x (one bh). 4 warps; warp owns 16 q rows.
// S tile = Q Kj^T (3xTF32) + qe-bias gather; online softmax; O += P Vj (3xTF32).
// =====================================================================
#define KSTR 68
#define VSTR 72
#define PSTR 68
#define QSTR 66
#define ATTN_SMEM ((64 * (KSTR + VSTR + PSTR + QSTR)) * 4)

__global__ __launch_bounds__(128) void attn_k(float scale) {
    extern __shared__ float sm[];
    float* Ks  = sm;
    float* Vs  = Ks + 64 * KSTR;
    float* Ps  = Vs + 64 * VSTR;
    float* QEs = Ps + 64 * PSTR;

    const int tid = threadIdx.x, lane = tid & 31, w = tid >> 5;
    const int r = lane >> 2, cc = lane & 3, wr = w * 16;
    const int q0 = blockIdx.x * 64;
    const int bh = blockIdx.y;

    const float* Qg  = g_Q + ((size_t)bh * S_LEN + q0) * HDIM;
    const float* Kg  = g_K + (size_t)bh * S_LEN * HDIM;
    const float* Vg  = g_V + (size_t)bh * S_LEN * HDIM;
    const float* QEg = g_QE + ((size_t)bh * S_LEN + q0) * NREL;

    // stage Q tile into Ps, load qe tile
    for (int i = tid; i < 64 * 16; i += 128) {
        int row = i >> 4, cf = (i & 15) << 2;
        *(float4*)(Ps + row * PSTR + cf) = *(const float4*)(Qg + row * HDIM + cf);
    }
    for (int row = w; row < 64; row += 4)
        for (int v = lane; v < NREL; v += 32)
            QEs[row * QSTR + v] = QEg[row * NREL + v];
    __syncthreads();

    // Q fragments (scale folded in), hi/lo split, persistent in registers
    uint32_t qhi[8][4], qlo[8][4];
#pragma unroll
    for (int ks = 0; ks < 8; ks++) {
        int col = ks * 8 + cc;
        float v0 = Ps[(wr + r) * PSTR + col] * scale;
        float v1 = Ps[(wr + r + 8) * PSTR + col] * scale;
        float v2 = Ps[(wr + r) * PSTR + col + 4] * scale;
        float v3 = Ps[(wr + r + 8) * PSTR + col + 4] * scale;
        tsplit(v0, qhi[ks][0], qlo[ks][0]);
        tsplit(v1, qhi[ks][1], qlo[ks][1]);
        tsplit(v2, qhi[ks][2], qlo[ks][2]);
        tsplit(v3, qhi[ks][3], qlo[ks][3]);
    }

    float o[8][4];
#pragma unroll
    for (int i = 0; i < 8; i++)
#pragma unroll
        for (int e = 0; e < 4; e++) o[i][e] = 0.f;
    float m0 = -1e30f, m1 = -1e30f, l0 = 0.f, l1 = 0.f;

    for (int j = 0; j < 32; j++) {
        __syncthreads();  // previous tile fully consumed
        const float* kg = Kg + (size_t)j * 64 * HDIM;
        const float* vg = Vg + (size_t)j * 64 * HDIM;
        for (int i = tid; i < 64 * 16; i += 128) {
            int row = i >> 4, cf = (i & 15) << 2;
            *(float4*)(Ks + row * KSTR + cf) = *(const float4*)(kg + row * HDIM + cf);
            *(float4*)(Vs + row * VSTR + cf) = *(const float4*)(vg + row * HDIM + cf);
        }
        __syncthreads();

        // ---- S = (Q*scale) K^T ----
        float sc[8][4];
#pragma unroll
        for (int ni = 0; ni < 8; ni++)
#pragma unroll
            for (int e = 0; e < 4; e++) sc[ni][e] = 0.f;

#pragma unroll
        for (int ks = 0; ks < 8; ks++) {
#pragma unroll
            for (int ni = 0; ni < 8; ni++) {
                int krow = ni * 8 + r, kk = ks * 8 + cc;
                float b0 = Ks[krow * KSTR + kk];
                float b1 = Ks[krow * KSTR + kk + 4];
                uint32_t bh_[2], bl_[2];
                tsplit(b0, bh_[0], bl_[0]);
                tsplit(b1, bh_[1], bl_[1]);
                mma8(sc[ni], qhi[ks], bh_);
                mma8(sc[ni], qhi[ks], bl_);
                mma8(sc[ni], qlo[ks], bh_);
            }
        }

        // ---- add relative-position bias ----
        const int k0 = j * 64;
#pragma unroll
        for (int ni = 0; ni < 8; ni++)
#pragma unroll
            for (int e = 0; e < 4; e++) {
                int ql = wr + r + ((e >> 1) << 3);
                int key = k0 + ni * 8 + (cc << 1) + (e & 1);
                int d2 = (q0 + ql) - key;
                d2 = d2 < -32 ? -32 : (d2 > 32 ? 32 : d2);
                sc[ni][e] += QEs[ql * QSTR + d2 + 32];
            }

        // ---- online softmax (rows r, r+8; 4 lanes share a row) ----
        float mx0 = -1e30f, mx1 = -1e30f;
#pragma unroll
        for (int ni = 0; ni < 8; ni++) {
            mx0 = fmaxf(mx0, fmaxf(sc[ni][0], sc[ni][1]));
            mx1 = fmaxf(mx1, fmaxf(sc[ni][2], sc[ni][3]));
        }
        mx0 = fmaxf(mx0, __shfl_xor_sync(0xffffffffu, mx0, 1));
        mx0 = fmaxf(mx0, __shfl_xor_sync(0xffffffffu, mx0, 2));
        mx1 = fmaxf(mx1, __shfl_xor_sync(0xffffffffu, mx1, 1));
        mx1 = fmaxf(mx1, __shfl_xor_sync(0xffffffffu, mx1, 2));

        float mn0 = fmaxf(m0, mx0), mn1 = fmaxf(m1, mx1);
        float al0 = __expf(m0 - mn0), al1 = __expf(m1 - mn1);
        float s0 = 0.f, s1 = 0.f;
#pragma unroll
        for (int ni = 0; ni < 8; ni++) {
            float p0 = __expf(sc[ni][0] - mn0);
            float p1 = __expf(sc[ni][1] - mn0);
            float p2 = __expf(sc[ni][2] - mn1);
            float p3 = __expf(sc[ni][3] - mn1);
            s0 += p0 + p1;
            s1 += p2 + p3;
            int col = ni * 8 + (cc << 1);
            Ps[(wr + r) * PSTR + col]     = p0;
            Ps[(wr + r) * PSTR + col + 1] = p1;
            Ps[(wr + r + 8) * PSTR + col]     = p2;
            Ps[(wr + r + 8) * PSTR + col + 1] = p3;
        }
        s0 += __shfl_xor_sync(0xffffffffu, s0, 1);
        s0 += __shfl_xor_sync(0xffffffffu, s0, 2);
        s1 += __shfl_xor_sync(0xffffffffu, s1, 1);
        s1 += __shfl_xor_sync(0xffffffffu, s1, 2);
        l0 = l0 * al0 + s0;
        l1 = l1 * al1 + s1;
        m0 = mn0;
        m1 = mn1;
#pragma unroll
        for (int ni = 0; ni < 8; ni++) {
            o[ni][0] *= al0; o[ni][1] *= al0;
            o[ni][2] *= al1; o[ni][3] *= al1;
        }
        __syncwarp();  // P rows are warp-private; order stores before frag loads

        // ---- O += P V ----
#pragma unroll
        for (int ks = 0; ks < 8; ks++) {
            int col = ks * 8 + cc;
            float p0v = Ps[(wr + r) * PSTR + col];
            float p1v = Ps[(wr + r + 8) * PSTR + col];
            float p2v = Ps[(wr + r) * PSTR + col + 4];
            float p3v = Ps[(wr + r + 8) * PSTR + col + 4];
            uint32_t ph[4], pl[4];
            tsplit(p0v, ph[0], pl[0]);
            tsplit(p1v, ph[1], pl[1]);
            tsplit(p2v, ph[2], pl[2]);
            tsplit(p3v, ph[3], pl[3]);
#pragma unroll
            for (int ni = 0; ni < 8; ni++) {
                float b0 = Vs[(ks * 8 + cc) * VSTR + ni * 8 + r];
                float b1 = Vs[(ks * 8 + cc + 4) * VSTR + ni * 8 + r];
                uint32_t bh_[2], bl_[2];
                tsplit(b0, bh_[0], bl_[0]);
                tsplit(b1, bh_[1], bl_[1]);
                mma8(o[ni], ph, bh_);
                mma8(o[ni], ph, bl_);
                mma8(o[ni], pl, bh_);
            }
        }
    }

    // ---- normalize + write O ----
    float inv0 = 1.f / l0, inv1 = 1.f / l1;
    float* Og = g_O + ((size_t)bh * S_LEN + q0) * HDIM;
#pragma unroll
    for (int ni = 0; ni < 8; ni++) {
        int col = ni * 8 + (cc << 1);
        *(float2*)(Og + (wr + r) * HDIM + col) =
            make_float2(o[ni][0] * inv0, o[ni][1] * inv0);
        *(float2*)(Og + (wr + r + 8) * HDIM + col) =
            make_float2(o[ni][2] * inv1, o[ni][3] * inv1);
    }
}

// =====================================================================
extern "C" void kernel_launch(void* const* d_in, const int* in_sizes, int n_in,
                              void* d_out, int out_size) {
    (void)in_sizes; (void)n_in; (void)out_size;
    const float* x   = (const float*)d_in[0];
    const float* Wq  = (const float*)d_in[1];
    const float* Wk  = (const float*)d_in[2];
    const float* Wv  = (const float*)d_in[3];
    const float* Wo  = (const float*)d_in[4];
    const float* bo  = (const float*)d_in[5];
    const float* rel = (const float*)d_in[6];
    float* out = (float*)d_out;

    dim3 gg(ND / GBN, NM / GBM);  // (8, 32)
    gemm_k<0><<<gg, 256>>>(x, Wq, nullptr, nullptr);
    gemm_k<1><<<gg, 256>>>(x, Wk, nullptr, nullptr);
    gemm_k<2><<<gg, 256>>>(x, Wv, nullptr, nullptr);

    qe_k<<<NBH * S_LEN / 8, 256>>>(rel);

    cudaFuncSetAttribute((const void*)attn_k,
                         cudaFuncAttributeMaxDynamicSharedMemorySize, ATTN_SMEM);
    attn_k<<<dim3(S_LEN / 64, NBH), 128, ATTN_SMEM>>>(0.125f);

    gemm_k<3><<<gg, 256>>>(x, Wo, bo, out);
}

// round 2
// speedup vs baseline: 1.8311x; 1.8311x over previous
#include <cuda_runtime.h>
#include <cuda_fp16.h>
#include <cstdint>

#define S_LEN 2048
#define NHEAD 16
#define HDIM  64
#define NREL  65
#define NBH   32
#define NM    4096
#define ND    1024

// ---------------- static device scratch ----------------
__device__ uint32_t g_xp[NM * ND];          // packed (hi,lo) halves of x
__device__ uint32_t g_Wp[4 * ND * ND];      // packed weights (Wq pre-scaled by 1/8)
__device__ uint32_t g_Qp[NBH * S_LEN * HDIM];
__device__ uint32_t g_Kp[NBH * S_LEN * HDIM];
__device__ uint32_t g_Vp[NBH * S_LEN * HDIM];
__device__ float    g_O [NBH * S_LEN * HDIM];

// ---------------- helpers ----------------
__device__ __forceinline__ uint32_t prm_hi(uint32_t a, uint32_t b){ return __byte_perm(a, b, 0x5410); }
__device__ __forceinline__ uint32_t prm_lo(uint32_t a, uint32_t b){ return __byte_perm(a, b, 0x7632); }

// pack fp32 -> (fp16 hi | fp16 lo<<16); hi+lo reproduces v to ~2^-22
__device__ __forceinline__ uint32_t packsplit(float v){
    __half h = __float2half_rn(v);
    __half l = __float2half_rn(v - __half2float(h));
    return (uint32_t)__half_as_ushort(h) | ((uint32_t)__half_as_ushort(l) << 16);
}

__device__ __forceinline__ void hsplit2(float a, float b, uint32_t& hi2, uint32_t& lo2){
    uint32_t pa = packsplit(a), pb = packsplit(b);
    hi2 = prm_hi(pa, pb);
    lo2 = prm_lo(pa, pb);
}

__device__ __forceinline__ void mma16(float* c, const uint32_t* a, const uint32_t* b){
    asm volatile(
        "mma.sync.aligned.m16n8k16.row.col.f32.f16.f16.f32 "
        "{%0,%1,%2,%3}, {%4,%5,%6,%7}, {%8,%9}, {%0,%1,%2,%3};\n"
        : "+f"(c[0]), "+f"(c[1]), "+f"(c[2]), "+f"(c[3])
        : "r"(a[0]), "r"(a[1]), "r"(a[2]), "r"(a[3]), "r"(b[0]), "r"(b[1]));
}

// ---------------- pre-pack kernel ----------------
__global__ void conv_k(const float* __restrict__ in, int dst, int n, float scale){
    int i = (blockIdx.x * blockDim.x + threadIdx.x) << 2;
    if (i >= n) return;
    uint32_t* out = (dst == 0) ? g_xp : (g_Wp + (size_t)(dst - 1) * ND * ND);
    float4 v = *(const float4*)(in + i);
    out[i + 0] = packsplit(v.x * scale);
    out[i + 1] = packsplit(v.y * scale);
    out[i + 2] = packsplit(v.z * scale);
    out[i + 3] = packsplit(v.w * scale);
}

// =====================================================================
// GEMM: C[m,n] = sum_k A[m,k] * W[n,k]   (fp16-split, mma.m16n8k16)
// MODE 0/1/2: A = g_xp (packed), write packed head layout to g_Qp/Kp/Vp
// MODE 3:     A = g_O fp32 (head-layout gather), write fp32 d_out + bias
// =====================================================================
#define GBM 128
#define GBN 128
#define SAH 24      // smem half stride (conflict-free frag reads)

template <int MODE>
__global__ __launch_bounds__(256) void gemm_k(const float* __restrict__ bias,
                                              float* __restrict__ Cout) {
    __shared__ __align__(16) __half As[2][2][GBM * SAH];   // [buf][hi/lo]
    __shared__ __align__(16) __half Bs[2][2][GBN * SAH];

    const int tid = threadIdx.x, lane = tid & 31, wrp = tid >> 5;
    const int gid = lane >> 2, tq = lane & 3;
    const int wm = (wrp >> 2) * 64, wn = (wrp & 3) * 32;
    const int m0 = blockIdx.y * GBM, n0 = blockIdx.x * GBN;

    const uint32_t* Bp = g_Wp + (size_t)((MODE == 3) ? 3 : MODE) * ND * ND;

    float acc[4][4][4];
#pragma unroll
    for (int i = 0; i < 4; i++)
#pragma unroll
        for (int j = 0; j < 4; j++)
#pragma unroll
            for (int e = 0; e < 4; e++) acc[i][j][e] = 0.f;

    uint4 ra[2], rb[2];
    float4 raf[2];

    auto ldA = [&](int kc) {
#pragma unroll
        for (int i = 0; i < 2; i++) {
            int idx = tid + (i << 8);
            int row = idx >> 2, kf = (idx & 3) << 2;
            if (MODE == 3) {
                int m = m0 + row, k = kc + kf;
                int b = m >> 11, s = m & 2047, h = k >> 6, d = k & 63;
                raf[i] = *(const float4*)(g_O + ((((size_t)(b * NHEAD + h)) * S_LEN + s) * HDIM + d));
            } else {
                ra[i] = *(const uint4*)(g_xp + (size_t)(m0 + row) * ND + kc + kf);
            }
        }
    };
    auto ldB = [&](int kc) {
#pragma unroll
        for (int i = 0; i < 2; i++) {
            int idx = tid + (i << 8);
            int row = idx >> 2, kf = (idx & 3) << 2;
            rb[i] = *(const uint4*)(Bp + (size_t)(n0 + row) * ND + kc + kf);
        }
    };
    auto sts = [&](int buf) {
#pragma unroll
        for (int i = 0; i < 2; i++) {
            int idx = tid + (i << 8);
            int row = idx >> 2, kf = (idx & 3) << 2;
            uint32_t w0, w1, w2, w3;
            if (MODE == 3) {
                w0 = packsplit(raf[i].x); w1 = packsplit(raf[i].y);
                w2 = packsplit(raf[i].z); w3 = packsplit(raf[i].w);
            } else {
                w0 = ra[i].x; w1 = ra[i].y; w2 = ra[i].z; w3 = ra[i].w;
            }
            *(uint32_t*)&As[buf][0][row * SAH + kf]     = prm_hi(w0, w1);
            *(uint32_t*)&As[buf][0][row * SAH + kf + 2] = prm_hi(w2, w3);
            *(uint32_t*)&As[buf][1][row * SAH + kf]     = prm_lo(w0, w1);
            *(uint32_t*)&As[buf][1][row * SAH + kf + 2] = prm_lo(w2, w3);
            *(uint32_t*)&Bs[buf][0][row * SAH + kf]     = prm_hi(rb[i].x, rb[i].y);
            *(uint32_t*)&Bs[buf][0][row * SAH + kf + 2] = prm_hi(rb[i].z, rb[i].w);
            *(uint32_t*)&Bs[buf][1][row * SAH + kf]     = prm_lo(rb[i].x, rb[i].y);
            *(uint32_t*)&Bs[buf][1][row * SAH + kf + 2] = prm_lo(rb[i].z, rb[i].w);
        }
    };

    ldA(0); ldB(0); sts(0);
    __syncthreads();

    for (int c = 0; c < 64; c++) {
        int buf = c & 1;
        if (c < 63) { ldA((c + 1) << 4); ldB((c + 1) << 4); }

        uint32_t ahi[4][4], alo[4][4];
#pragma unroll
        for (int mi = 0; mi < 4; mi++) {
            int rb0 = (wm + mi * 16 + gid) * SAH;
            int rb1 = rb0 + 8 * SAH;
            ahi[mi][0] = *(const uint32_t*)&As[buf][0][rb0 + 2 * tq];
            ahi[mi][1] = *(const uint32_t*)&As[buf][0][rb1 + 2 * tq];
            ahi[mi][2] = *(const uint32_t*)&As[buf][0][rb0 + 2 * tq + 8];
            ahi[mi][3] = *(const uint32_t*)&As[buf][0][rb1 + 2 * tq + 8];
            alo[mi][0] = *(const uint32_t*)&As[buf][1][rb0 + 2 * tq];
            alo[mi][1] = *(const uint32_t*)&As[buf][1][rb1 + 2 * tq];
            alo[mi][2] = *(const uint32_t*)&As[buf][1][rb0 + 2 * tq + 8];
            alo[mi][3] = *(const uint32_t*)&As[buf][1][rb1 + 2 * tq + 8];
        }
#pragma unroll
        for (int ni = 0; ni < 4; ni++) {
            int nb = (wn + ni * 8 + gid) * SAH;
            uint32_t bh[2], bl[2];
            bh[0] = *(const uint32_t*)&Bs[buf][0][nb + 2 * tq];
            bh[1] = *(const uint32_t*)&Bs[buf][0][nb + 2 * tq + 8];
            bl[0] = *(const uint32_t*)&Bs[buf][1][nb + 2 * tq];
            bl[1] = *(const uint32_t*)&Bs[buf][1][nb + 2 * tq + 8];
#pragma unroll
            for (int mi = 0; mi < 4; mi++) {
                mma16(acc[mi][ni], ahi[mi], bh);
                mma16(acc[mi][ni], ahi[mi], bl);
                mma16(acc[mi][ni], alo[mi], bh);
            }
        }
        if (c < 63) { sts(buf ^ 1); __syncthreads(); }
    }

    // epilogue
#pragma unroll
    for (int mi = 0; mi < 4; mi++)
#pragma unroll
        for (int ni = 0; ni < 4; ni++)
#pragma unroll
            for (int half = 0; half < 2; half++) {
                int row = m0 + wm + mi * 16 + gid + half * 8;
                int col = n0 + wn + ni * 8 + tq * 2;
                float v0 = acc[mi][ni][half * 2];
                float v1 = acc[mi][ni][half * 2 + 1];
                if (MODE == 3) {
                    v0 += bias[col];
                    v1 += bias[col + 1];
                    *(float2*)(Cout + (size_t)row * ND + col) = make_float2(v0, v1);
                } else {
                    uint32_t* dst = (MODE == 0) ? g_Qp : (MODE == 1) ? g_Kp : g_Vp;
                    int b = row >> 11, s = row & 2047, h = col >> 6, d = col & 63;
                    *(uint2*)(dst + (((size_t)(b * NHEAD + h)) * S_LEN + s) * HDIM + d) =
                        make_uint2(packsplit(v0), packsplit(v1));
                }
            }
}

// =====================================================================
// Flash attention, fp16-split mma. CTA = 64 q x one bh, 4 warps.
// qe (rel bias table) computed in prologue via mma against scaled rel.
// =====================================================================
#define SKH 72      // K smem half stride
#define SVH 72      // Vt smem half stride
#define SPH 72      // P smem half stride
#define QEW 68      // QE fp32 stride
#define VSTG 65     // V fp32-word staging stride
#define ASMEM 72704

__global__ __launch_bounds__(128) void attn_k(const float* __restrict__ rel) {
    extern __shared__ char smraw[];
    __half* Khi  = (__half*)smraw;                     //  0     .. 9216
    __half* Klo  = Khi + 64 * SKH;                     //  9216  .. 18432
    __half* Vthi = (__half*)(smraw + 18432);           // 18432  .. 27648
    __half* Vtlo = Vthi + 64 * SVH;                    // 27648  .. 36864
    __half* Phi  = (__half*)(smraw + 36864);           // 36864  .. 46080
    __half* Plo  = Phi + 64 * SPH;                     // 46080  .. 55296
    float*  QEs  = (float*)(smraw + 55296);            // 55296  .. 72704
    // prologue overlays
    __half* relhi = (__half*)smraw;                    // 72*72 halves
    __half* rello = relhi + 72 * 72;
    uint32_t* Qst   = (uint32_t*)(smraw + 36864);      // 64*64 words
    uint32_t* stage = (uint32_t*)(smraw + 36864);      // 64*65 words (loop)

    const int tid = threadIdx.x, lane = tid & 31, w = tid >> 5;
    const int gid = lane >> 2, tq = lane & 3, wr = w * 16;
    const int q0 = blockIdx.x * 64;
    const int bh = blockIdx.y;

    const uint32_t* Qg = g_Qp + ((size_t)bh * S_LEN + q0) * HDIM;
    const uint32_t* Kg = g_Kp + (size_t)bh * S_LEN * HDIM;
    const uint32_t* Vg = g_Vp + (size_t)bh * S_LEN * HDIM;

    // ---- prologue: stage Q (packed) + rel (x8, split) ----
#pragma unroll
    for (int s = 0; s < 8; s++) {
        int i = tid + s * 128;
        int row = i >> 4, wq = (i & 15) << 2;
        *(uint4*)&Qst[row * 64 + wq] = *(const uint4*)(Qg + row * 64 + wq);
    }
    for (int i = tid; i < 72 * 64; i += 128) {
        int v = i >> 6, d = i & 63;
        float rv = (v < NREL) ? rel[v * 64 + d] * 8.0f : 0.f;
        uint32_t p = packsplit(rv);
        relhi[v * 72 + d] = __ushort_as_half((unsigned short)(p & 0xffff));
        rello[v * 72 + d] = __ushort_as_half((unsigned short)(p >> 16));
    }
    __syncthreads();

    // Q fragments (Q already carries the 1/8 scale from Wq pre-scaling)
    uint32_t qhi[4][4], qlo[4][4];
#pragma unroll
    for (int kc = 0; kc < 4; kc++) {
        int b0 = (wr + gid) * 64 + kc * 16;
        int b1 = (wr + gid + 8) * 64 + kc * 16;
        uint32_t w0, w1;
        w0 = Qst[b0 + 2 * tq];     w1 = Qst[b0 + 2 * tq + 1];
        qhi[kc][0] = prm_hi(w0, w1); qlo[kc][0] = prm_lo(w0, w1);
        w0 = Qst[b1 + 2 * tq];     w1 = Qst[b1 + 2 * tq + 1];
        qhi[kc][1] = prm_hi(w0, w1); qlo[kc][1] = prm_lo(w0, w1);
        w0 = Qst[b0 + 2 * tq + 8]; w1 = Qst[b0 + 2 * tq + 9];
        qhi[kc][2] = prm_hi(w0, w1); qlo[kc][2] = prm_lo(w0, w1);
        w0 = Qst[b1 + 2 * tq + 8]; w1 = Qst[b1 + 2 * tq + 9];
        qhi[kc][3] = prm_hi(w0, w1); qlo[kc][3] = prm_lo(w0, w1);
    }

    // qe = (Q/8) . (8*rel)^T  via mma, 9 n-tiles covering v=0..64
#pragma unroll
    for (int ni = 0; ni < 9; ni++) {
        float qe[4] = {0.f, 0.f, 0.f, 0.f};
#pragma unroll
        for (int kc = 0; kc < 4; kc++) {
            int nb = (ni * 8 + gid) * 72 + kc * 16;
            uint32_t bh_[2], bl_[2];
            bh_[0] = *(const uint32_t*)&relhi[nb + 2 * tq];
            bh_[1] = *(const uint32_t*)&relhi[nb + 2 * tq + 8];
            bl_[0] = *(const uint32_t*)&rello[nb + 2 * tq];
            bl_[1] = *(const uint32_t*)&rello[nb + 2 * tq + 8];
            mma16(qe, qhi[kc], bh_);
            mma16(qe, qhi[kc], bl_);
            mma16(qe, qlo[kc], bh_);
        }
        int col = ni * 8 + 2 * tq;
        if (col < NREL) {
            QEs[(wr + gid) * QEW + col]     = qe[0];
            QEs[(wr + gid + 8) * QEW + col] = qe[2];
        }
        if (col + 1 < NREL) {
            QEs[(wr + gid) * QEW + col + 1]     = qe[1];
            QEs[(wr + gid + 8) * QEW + col + 1] = qe[3];
        }
    }

    float o[8][4];
#pragma unroll
    for (int i = 0; i < 8; i++)
#pragma unroll
        for (int e = 0; e < 4; e++) o[i][e] = 0.f;
    float m0 = -1e30f, m1 = -1e30f, l0 = 0.f, l1 = 0.f;

    for (int j = 0; j < 32; j++) {
        __syncthreads();  // prev tile fully consumed (incl. P read by PV)
        const uint32_t* kg = Kg + (size_t)j * 64 * HDIM;
        const uint32_t* vg = Vg + (size_t)j * 64 * HDIM;
#pragma unroll
        for (int s = 0; s < 8; s++) {
            int i = tid + s * 128;
            int row = i >> 4, wq = (i & 15) << 2;
            uint4 kv = *(const uint4*)(kg + row * 64 + wq);
            *(uint32_t*)&Khi[row * SKH + wq]     = prm_hi(kv.x, kv.y);
            *(uint32_t*)&Khi[row * SKH + wq + 2] = prm_hi(kv.z, kv.w);
            *(uint32_t*)&Klo[row * SKH + wq]     = prm_lo(kv.x, kv.y);
            *(uint32_t*)&Klo[row * SKH + wq + 2] = prm_lo(kv.z, kv.w);
            uint4 vv = *(const uint4*)(vg + row * 64 + wq);
            stage[row * VSTG + wq]     = vv.x;
            stage[row * VSTG + wq + 1] = vv.y;
            stage[row * VSTG + wq + 2] = vv.z;
            stage[row * VSTG + wq + 3] = vv.w;
        }
        __syncthreads();

        // ---- V transpose into Vt planes ----
        {
            int p = lane, g = w;
#pragma unroll
            for (int it = 0; it < 16; it++) {
                int d = g * 16 + it;
                uint32_t w0 = stage[(2 * p) * VSTG + d];
                uint32_t w1 = stage[(2 * p + 1) * VSTG + d];
                *(uint32_t*)&Vthi[d * SVH + 2 * p] = prm_hi(w0, w1);
                *(uint32_t*)&Vtlo[d * SVH + 2 * p] = prm_lo(w0, w1);
            }
        }

        // ---- S = Qs K^T ----
        float sc[8][4];
#pragma unroll
        for (int ni = 0; ni < 8; ni++)
#pragma unroll
            for (int e = 0; e < 4; e++) sc[ni][e] = 0.f;
#pragma unroll
        for (int kc = 0; kc < 4; kc++) {
#pragma unroll
            for (int ni = 0; ni < 8; ni++) {
                int nb = (ni * 8 + gid) * SKH + kc * 16;
                uint32_t bh_[2], bl_[2];
                bh_[0] = *(const uint32_t*)&Khi[nb + 2 * tq];
                bh_[1] = *(const uint32_t*)&Khi[nb + 2 * tq + 8];
                bl_[0] = *(const uint32_t*)&Klo[nb + 2 * tq];
                bl_[1] = *(const uint32_t*)&Klo[nb + 2 * tq + 8];
                mma16(sc[ni], qhi[kc], bh_);
                mma16(sc[ni], qhi[kc], bl_);
                mma16(sc[ni], qlo[kc], bh_);
            }
        }

        // ---- relative-position bias ----
        const int k0 = j * 64;
#pragma unroll
        for (int ni = 0; ni < 8; ni++)
#pragma unroll
            for (int e = 0; e < 4; e++) {
                int ql = wr + gid + ((e >> 1) << 3);
                int key = k0 + ni * 8 + (tq << 1) + (e & 1);
                int d2 = (q0 + ql) - key;
                d2 = d2 < -32 ? -32 : (d2 > 32 ? 32 : d2);
                sc[ni][e] += QEs[ql * QEW + d2 + 32];
            }

        __syncthreads();  // Vt ready everywhere; stage region free for P

        // ---- online softmax ----
        float mx0 = -1e30f, mx1 = -1e30f;
#pragma unroll
        for (int ni = 0; ni < 8; ni++) {
            mx0 = fmaxf(mx0, fmaxf(sc[ni][0], sc[ni][1]));
            mx1 = fmaxf(mx1, fmaxf(sc[ni][2], sc[ni][3]));
        }
        mx0 = fmaxf(mx0, __shfl_xor_sync(0xffffffffu, mx0, 1));
        mx0 = fmaxf(mx0, __shfl_xor_sync(0xffffffffu, mx0, 2));
        mx1 = fmaxf(mx1, __shfl_xor_sync(0xffffffffu, mx1, 1));
        mx1 = fmaxf(mx1, __shfl_xor_sync(0xffffffffu, mx1, 2));

        float mn0 = fmaxf(m0, mx0), mn1 = fmaxf(m1, mx1);
        float al0 = __expf(m0 - mn0), al1 = __expf(m1 - mn1);
        float s0 = 0.f, s1 = 0.f;
#pragma unroll
        for (int ni = 0; ni < 8; ni++) {
            float p0 = __expf(sc[ni][0] - mn0);
            float p1 = __expf(sc[ni][1] - mn0);
            float p2 = __expf(sc[ni][2] - mn1);
            float p3 = __expf(sc[ni][3] - mn1);
            s0 += p0 + p1;
            s1 += p2 + p3;
            int col = ni * 8 + (tq << 1);
            uint32_t h2, l2;
            hsplit2(p0, p1, h2, l2);
            *(uint32_t*)&Phi[(wr + gid) * SPH + col] = h2;
            *(uint32_t*)&Plo[(wr + gid) * SPH + col] = l2;
            hsplit2(p2, p3, h2, l2);
            *(uint32_t*)&Phi[(wr + gid + 8) * SPH + col] = h2;
            *(uint32_t*)&Plo[(wr + gid + 8) * SPH + col] = l2;
        }
        s0 += __shfl_xor_sync(0xffffffffu, s0, 1);
        s0 += __shfl_xor_sync(0xffffffffu, s0, 2);
        s1 += __shfl_xor_sync(0xffffffffu, s1, 1);
        s1 += __shfl_xor_sync(0xffffffffu, s1, 2);
        l0 = l0 * al0 + s0;
        l1 = l1 * al1 + s1;
        m0 = mn0;
        m1 = mn1;
#pragma unroll
        for (int ni = 0; ni < 8; ni++) {
            o[ni][0] *= al0; o[ni][1] *= al0;
            o[ni][2] *= al1; o[ni][3] *= al1;
        }
        __syncwarp();  // P rows are warp-private

        // ---- O += P V ----
#pragma unroll
        for (int kc = 0; kc < 4; kc++) {
            int pb0 = (wr + gid) * SPH + kc * 16;
            int pb1 = (wr + gid + 8) * SPH + kc * 16;
            uint32_t ah[4], al_[4];
            ah[0] = *(const uint32_t*)&Phi[pb0 + 2 * tq];
            ah[1] = *(const uint32_t*)&Phi[pb1 + 2 * tq];
            ah[2] = *(const uint32_t*)&Phi[pb0 + 2 * tq + 8];
            ah[3] = *(const uint32_t*)&Phi[pb1 + 2 * tq + 8];
            al_[0] = *(const uint32_t*)&Plo[pb0 + 2 * tq];
            al_[1] = *(const uint32_t*)&Plo[pb1 + 2 * tq];
            al_[2] = *(const uint32_t*)&Plo[pb0 + 2 * tq + 8];
            al_[3] = *(const uint32_t*)&Plo[pb1 + 2 * tq + 8];
#pragma unroll
            for (int ni = 0; ni < 8; ni++) {
                int vb = (ni * 8 + gid) * SVH + kc * 16;
                uint32_t bh_[2], bl_[2];
                bh_[0] = *(const uint32_t*)&Vthi[vb + 2 * tq];
                bh_[1] = *(const uint32_t*)&Vthi[vb + 2 * tq + 8];
                bl_[0] = *(const uint32_t*)&Vtlo[vb + 2 * tq];
                bl_[1] = *(const uint32_t*)&Vtlo[vb + 2 * tq + 8];
                mma16(o[ni], ah, bh_);
                mma16(o[ni], ah, bl_);
                mma16(o[ni], al_, bh_);
            }
        }
    }

    // ---- normalize + write O (fp32 head layout) ----
    float inv0 = 1.f / l0, inv1 = 1.f / l1;
    float* Og = g_O + ((size_t)bh * S_LEN + q0) * HDIM;
#pragma unroll
    for (int ni = 0; ni < 8; ni++) {
        int col = ni * 8 + (tq << 1);
        *(float2*)(Og + (wr + gid) * HDIM + col) =
            make_float2(o[ni][0] * inv0, o[ni][1] * inv0);
        *(float2*)(Og + (wr + gid + 8) * HDIM + col) =
            make_float2(o[ni][2] * inv1, o[ni][3] * inv1);
    }
}

// =====================================================================
extern "C" void kernel_launch(void* const* d_in, const int* in_sizes, int n_in,
                              void* d_out, int out_size) {
    (void)in_sizes; (void)n_in; (void)out_size;
    const float* x   = (const float*)d_in[0];
    const float* Wq  = (const float*)d_in[1];
    const float* Wk  = (const float*)d_in[2];
    const float* Wv  = (const float*)d_in[3];
    const float* Wo  = (const float*)d_in[4];
    const float* bo  = (const float*)d_in[5];
    const float* rel = (const float*)d_in[6];
    float* out = (float*)d_out;

    conv_k<<<NM * ND / 4 / 256, 256>>>(x,  0, NM * ND, 1.0f);
    conv_k<<<ND * ND / 4 / 256, 256>>>(Wq, 1, ND * ND, 0.125f);  // fold attn scale
    conv_k<<<ND * ND / 4 / 256, 256>>>(Wk, 2, ND * ND, 1.0f);
    conv_k<<<ND * ND / 4 / 256, 256>>>(Wv, 3, ND * ND, 1.0f);
    conv_k<<<ND * ND / 4 / 256, 256>>>(Wo, 4, ND * ND, 1.0f);

    dim3 gg(ND / GBN, NM / GBM);  // (8, 32)
    gemm_k<0><<<gg, 256>>>(nullptr, nullptr);
    gemm_k<1><<<gg, 256>>>(nullptr, nullptr);
    gemm_k<2><<<gg, 256>>>(nullptr, nullptr);

    cudaFuncSetAttribute((const void*)attn_k,
                         cudaFuncAttributeMaxDynamicSharedMemorySize, ASMEM);
    attn_k<<<dim3(S_LEN / 64, NBH), 128, ASMEM>>>(rel);

    gemm_k<3><<<gg, 256>>>(bo, out);
}

// round 6
// speedup vs baseline: 1.9121x; 1.0443x over previous
#include <cuda_runtime.h>
#include <cuda_fp16.h>
#include <cstdint>

#define S_LEN 2048
#define NHEAD 16
#define HDIM  64
#define NREL  65
#define NBH   32
#define NM    4096
#define ND    1024

// ---------------- static device scratch: hi/lo half planes ----------------
__device__ __half g_xhi[NM * ND],  g_xlo[NM * ND];
__device__ __half g_Whi[4 * ND * ND], g_Wlo[4 * ND * ND];
__device__ __half g_Qh[NBH * S_LEN * HDIM], g_Ql[NBH * S_LEN * HDIM];
__device__ __half g_KhG[NBH * S_LEN * HDIM], g_KlG[NBH * S_LEN * HDIM];
__device__ __half g_VhG[NBH * S_LEN * HDIM], g_VlG[NBH * S_LEN * HDIM];
__device__ float  g_O[NBH * S_LEN * HDIM];

// ---------------- helpers ----------------
__device__ __forceinline__ uint32_t s2u(const void* p) {
    return (uint32_t)__cvta_generic_to_shared(p);
}
__device__ __forceinline__ void cpa16(uint32_t d, const void* s) {
    asm volatile("cp.async.cg.shared.global [%0], [%1], 16;\n" :: "r"(d), "l"(s));
}
#define CP_COMMIT() asm volatile("cp.async.commit_group;\n" ::)
#define CP_WAIT(n)  asm volatile("cp.async.wait_group %0;\n" :: "n"(n))

__device__ __forceinline__ void ldsm4(uint32_t& r0, uint32_t& r1, uint32_t& r2,
                                      uint32_t& r3, uint32_t a) {
    asm volatile("ldmatrix.sync.aligned.m8n8.x4.shared.b16 {%0,%1,%2,%3}, [%4];\n"
                 : "=r"(r0), "=r"(r1), "=r"(r2), "=r"(r3) : "r"(a));
}
__device__ __forceinline__ void ldsm4t(uint32_t& r0, uint32_t& r1, uint32_t& r2,
                                       uint32_t& r3, uint32_t a) {
    asm volatile("ldmatrix.sync.aligned.m8n8.x4.trans.shared.b16 {%0,%1,%2,%3}, [%4];\n"
                 : "=r"(r0), "=r"(r1), "=r"(r2), "=r"(r3) : "r"(a));
}
__device__ __forceinline__ void mma16(float* c, const uint32_t* a, const uint32_t* b) {
    asm volatile(
        "mma.sync.aligned.m16n8k16.row.col.f32.f16.f16.f32 "
        "{%0,%1,%2,%3}, {%4,%5,%6,%7}, {%8,%9}, {%0,%1,%2,%3};\n"
        : "+f"(c[0]), "+f"(c[1]), "+f"(c[2]), "+f"(c[3])
        : "r"(a[0]), "r"(a[1]), "r"(a[2]), "r"(a[3]), "r"(b[0]), "r"(b[1]));
}
__device__ __forceinline__ uint32_t h2u(__half a, __half b) {
    __half2 t = __halves2half2(a, b);
    return *(uint32_t*)&t;
}

// ---------------- split-convert kernel ----------------
__global__ void conv_k(const float* __restrict__ in, int which, int n, float scale) {
    int i = (blockIdx.x * blockDim.x + threadIdx.x) << 2;
    if (i >= n) return;
    __half *hi, *lo;
    if (which == 0) { hi = g_xhi; lo = g_xlo; }
    else { hi = g_Whi + (size_t)(which - 1) * ND * ND; lo = g_Wlo + (size_t)(which - 1) * ND * ND; }
    float4 v = *(const float4*)(in + i);
    float f0 = v.x * scale, f1 = v.y * scale, f2 = v.z * scale, f3 = v.w * scale;
    __half h0 = __float2half_rn(f0), h1 = __float2half_rn(f1);
    __half h2 = __float2half_rn(f2), h3 = __float2half_rn(f3);
    *(__half2*)&hi[i]     = __halves2half2(h0, h1);
    *(__half2*)&hi[i + 2] = __halves2half2(h2, h3);
    *(__half2*)&lo[i]     = __halves2half2(__float2half_rn(f0 - __half2float(h0)),
                                           __float2half_rn(f1 - __half2float(h1)));
    *(__half2*)&lo[i + 2] = __halves2half2(__float2half_rn(f2 - __half2float(h2)),
                                           __float2half_rn(f3 - __half2float(h3)));
}

// =====================================================================
// GEMM: C[m,n] = sum_k A[m,k] * W[n,k], fp16-split, cp.async + ldmatrix
// MODE 0/1/2: A = x planes, out = Q/K/V hi-lo planes (head layout)
// MODE 3:     A = g_O fp32 gather, out = fp32 d_out + bias
// =====================================================================
#define SAH 24                 // smem halves per row (48B, LDSM conflict-free)
#define GPLANE 3072            // halves per plane (128*24)
#define GBUFB 24576            // bytes per buffer (4 planes)

template <int MODE>
__global__ __launch_bounds__(256) void gemm_k(const float* __restrict__ bias,
                                              float* __restrict__ Cout) {
    __shared__ __align__(16) __half sm[2 * 4 * GPLANE];   // 48KB

    const int tid = threadIdx.x, lane = tid & 31, wrp = tid >> 5;
    const int gid = lane >> 2, tq = lane & 3;
    const int wm = (wrp >> 2) * 64, wn = (wrp & 3) * 32;
    const int m0 = blockIdx.y * 128, n0 = blockIdx.x * 128;
    const uint32_t smb = s2u(sm);

    const int wsel = (MODE == 3) ? 3 : MODE;
    const __half* Wh = g_Whi + (size_t)wsel * ND * ND;
    const __half* Wl = g_Wlo + (size_t)wsel * ND * ND;

    // ldmatrix fragment addresses (buf0)
    const int lb = lane >> 3, lr = lane & 7;
    const uint32_t addrA0 = smb + ((wm + (lb & 1) * 8 + lr) * SAH + (lb >> 1) * 8) * 2;
    const uint32_t addrB0 = smb + 2 * GPLANE * 2 +
                            ((wn + (lane >> 4) * 8 + lr) * SAH + ((lane >> 3) & 1) * 8) * 2;

    // cp.async dst addresses
    const int rowc = tid >> 1, chc = (tid & 1) * 8;
    const uint32_t dA = smb + (rowc * SAH + chc) * 2;
    const uint32_t dB = smb + 2 * GPLANE * 2 + (rowc * SAH + chc) * 2;
    const __half* srcAh = g_xhi + (size_t)(m0 + rowc) * ND + chc;
    const __half* srcAl = g_xlo + (size_t)(m0 + rowc) * ND + chc;
    const __half* srcBh = Wh + (size_t)(n0 + rowc) * ND + chc;
    const __half* srcBl = Wl + (size_t)(n0 + rowc) * ND + chc;

    float acc[4][4][4];
#pragma unroll
    for (int i = 0; i < 4; i++)
#pragma unroll
        for (int j = 0; j < 4; j++)
#pragma unroll
            for (int e = 0; e < 4; e++) acc[i][j][e] = 0.f;

    // MODE 3 synchronous staging state
    float4 raf[2];
    uint4 rbh, rbl;
    auto ld3 = [&](int kc) {
        if (MODE != 3) return;
#pragma unroll
        for (int i = 0; i < 2; i++) {
            int idx = tid + (i << 8);
            int row = idx >> 2, q4 = idx & 3;
            int m = m0 + row, k = kc + q4 * 4;
            int b = m >> 11, s = m & 2047, h = k >> 6, d = k & 63;
            raf[i] = *(const float4*)(g_O + ((((size_t)(b * NHEAD + h)) * S_LEN + s) * HDIM + d));
        }
        rbh = *(const uint4*)(srcBh + kc);
        rbl = *(const uint4*)(srcBl + kc);
    };
    auto sts3 = [&](int buf) {
        if (MODE != 3) return;
        uint32_t bo = buf * GBUFB;
#pragma unroll
        for (int i = 0; i < 2; i++) {
            int idx = tid + (i << 8);
            int row = idx >> 2, q4 = idx & 3;
            float f0 = raf[i].x, f1 = raf[i].y, f2 = raf[i].z, f3 = raf[i].w;
            __half h0 = __float2half_rn(f0), h1 = __float2half_rn(f1);
            __half h2 = __float2half_rn(f2), h3 = __float2half_rn(f3);
            __half* ph = (__half*)(sm) + buf * 4 * GPLANE + row * SAH + q4 * 4;
            __half* pl = ph + GPLANE;
            *(__half2*)ph       = __halves2half2(h0, h1);
            *(__half2*)(ph + 2) = __halves2half2(h2, h3);
            *(__half2*)pl       = __halves2half2(__float2half_rn(f0 - __half2float(h0)),
                                                 __float2half_rn(f1 - __half2float(h1)));
            *(__half2*)(pl + 2) = __halves2half2(__float2half_rn(f2 - __half2float(h2)),
                                                 __float2half_rn(f3 - __half2float(h3)));
        }
        *(uint4*)((char*)sm + bo + 2 * GPLANE * 2 + (rowc * SAH + chc) * 2) = rbh;
        *(uint4*)((char*)sm + bo + 3 * GPLANE * 2 + (rowc * SAH + chc) * 2) = rbl;
    };
    auto issueAsync = [&](int kc, int buf) {
        uint32_t bo = buf * GBUFB;
        cpa16(dA + bo,                   srcAh + kc);
        cpa16(dA + bo + GPLANE * 2,      srcAl + kc);
        cpa16(dB + bo,                   srcBh + kc);
        cpa16(dB + bo + GPLANE * 2,      srcBl + kc);
    };

    auto compute = [&](int buf) {
        uint32_t bo = buf * GBUFB;
        uint32_t ah[4][4], al[4][4];
#pragma unroll
        for (int mi = 0; mi < 4; mi++) {
            ldsm4(ah[mi][0], ah[mi][1], ah[mi][2], ah[mi][3],
                  addrA0 + bo + mi * 16 * SAH * 2);
            ldsm4(al[mi][0], al[mi][1], al[mi][2], al[mi][3],
                  addrA0 + bo + GPLANE * 2 + mi * 16 * SAH * 2);
        }
        uint32_t bh[4][2], bl[4][2];
#pragma unroll
        for (int p = 0; p < 2; p++) {
            ldsm4(bh[2 * p][0], bh[2 * p][1], bh[2 * p + 1][0], bh[2 * p + 1][1],
                  addrB0 + bo + p * 16 * SAH * 2);
            ldsm4(bl[2 * p][0], bl[2 * p][1], bl[2 * p + 1][0], bl[2 * p + 1][1],
                  addrB0 + bo + GPLANE * 2 + p * 16 * SAH * 2);
        }
#pragma unroll
        for (int ni = 0; ni < 4; ni++)
#pragma unroll
            for (int mi = 0; mi < 4; mi++) {
                mma16(acc[mi][ni], ah[mi], bh[ni]);
                mma16(acc[mi][ni], ah[mi], bl[ni]);
                mma16(acc[mi][ni], al[mi], bh[ni]);
            }
    };

    if (MODE == 3) {
        ld3(0); sts3(0);
        __syncthreads();
        for (int c = 0; c < 64; c++) {
            if (c < 63) ld3((c + 1) << 4);
            compute(c & 1);
            if (c < 63) {
                __syncthreads();
                sts3((c + 1) & 1);
                __syncthreads();
            }
        }
    } else {
        issueAsync(0, 0); CP_COMMIT();
        for (int c = 0; c < 64; c++) {
            if (c < 63) { issueAsync((c + 1) << 4, (c + 1) & 1); CP_COMMIT(); CP_WAIT(1); }
            else CP_WAIT(0);
            __syncthreads();
            compute(c & 1);
            __syncthreads();
        }
    }

    // epilogue
#pragma unroll
    for (int mi = 0; mi < 4; mi++)
#pragma unroll
        for (int ni = 0; ni < 4; ni++)
#pragma unroll
            for (int half_ = 0; half_ < 2; half_++) {
                int row = m0 + wm + mi * 16 + gid + half_ * 8;
                int col = n0 + wn + ni * 8 + tq * 2;
                float v0 = acc[mi][ni][half_ * 2];
                float v1 = acc[mi][ni][half_ * 2 + 1];
                if (MODE == 3) {
                    v0 += bias[col];
                    v1 += bias[col + 1];
                    *(float2*)(Cout + (size_t)row * ND + col) = make_float2(v0, v1);
                } else {
                    __half* dh = (MODE == 0) ? g_Qh : (MODE == 1) ? g_KhG : g_VhG;
                    __half* dl = (MODE == 0) ? g_Ql : (MODE == 1) ? g_KlG : g_VlG;
                    int b = row >> 11, s = row & 2047, h = col >> 6, d = col & 63;
                    size_t idx = (((size_t)(b * NHEAD + h)) * S_LEN + s) * HDIM + d;
                    __half h0 = __float2half_rn(v0), h1 = __float2half_rn(v1);
                    *(__half2*)&dh[idx] = __halves2half2(h0, h1);
                    *(__half2*)&dl[idx] =
                        __halves2half2(__float2half_rn(v0 - __half2float(h0)),
                                       __float2half_rn(v1 - __half2float(h1)));
                }
            }
}

// =====================================================================
// Flash attention: 128 q rows/CTA, 8 warps, cp.async double-buffered K/V,
// ldmatrix frags, P kept in registers, qe bias via mma in prologue.
// =====================================================================
#define AKVB 36864            // bytes per K/V buffer (4 planes of 64x72 halves)
#define A_KH 0
#define A_KL 9216
#define A_VH 18432
#define A_VL 27648
#define QEW  66
#define ASMEM (2 * AKVB + 128 * QEW * 4)   // 73728 + 33792 = 107520

__global__ __launch_bounds__(256) void attn_k(const float* __restrict__ rel) {
    extern __shared__ char smraw[];
    float* QEs = (float*)(smraw + 2 * AKVB);
    __half* relh = (__half*)smraw;            // prologue overlay (72x72)
    __half* rell = relh + 72 * 72;
    const uint32_t smb = s2u(smraw);

    const int tid = threadIdx.x, lane = tid & 31, w = tid >> 5;
    const int gid = lane >> 2, tq = lane & 3, wr = w * 16;
    const int q0 = blockIdx.x * 128;
    const int bh = blockIdx.y;
    const size_t kvbase = (size_t)bh * S_LEN * HDIM;

    // ---- prologue: rel staging (x8, split) ----
    for (int i = tid; i < 72 * 64; i += 256) {
        int v = i >> 6, d = i & 63;
        float rv = (v < NREL) ? rel[v * 64 + d] * 8.0f : 0.f;
        __half h = __float2half_rn(rv);
        relh[v * 72 + d] = h;
        rell[v * 72 + d] = __float2half_rn(rv - __half2float(h));
    }

    // ---- Q fragments from global planes (scale 1/8 folded into Wq) ----
    uint32_t qhi[4][4], qlo[4][4];
    {
        const size_t qb = ((size_t)bh * S_LEN + q0) * HDIM;
        const __half* qh = g_Qh + qb;
        const __half* ql = g_Ql + qb;
#pragma unroll
        for (int kc = 0; kc < 4; kc++) {
            int c0 = kc * 16 + 2 * tq;
            size_t r0 = (size_t)(wr + gid) * 64, r1 = (size_t)(wr + gid + 8) * 64;
            qhi[kc][0] = *(const uint32_t*)(qh + r0 + c0);
            qhi[kc][1] = *(const uint32_t*)(qh + r1 + c0);
            qhi[kc][2] = *(const uint32_t*)(qh + r0 + c0 + 8);
            qhi[kc][3] = *(const uint32_t*)(qh + r1 + c0 + 8);
            qlo[kc][0] = *(const uint32_t*)(ql + r0 + c0);
            qlo[kc][1] = *(const uint32_t*)(ql + r1 + c0);
            qlo[kc][2] = *(const uint32_t*)(ql + r0 + c0 + 8);
            qlo[kc][3] = *(const uint32_t*)(ql + r1 + c0 + 8);
        }
    }
    __syncthreads();

    // ---- qe = Q . rel^T via mma ----
#pragma unroll
    for (int ni = 0; ni < 9; ni++) {
        float qe[4] = {0.f, 0.f, 0.f, 0.f};
#pragma unroll
        for (int kc = 0; kc < 4; kc++) {
            int nb = (ni * 8 + gid) * 72 + kc * 16 + 2 * tq;
            uint32_t bh_[2], bl_[2];
            bh_[0] = *(const uint32_t*)&relh[nb];
            bh_[1] = *(const uint32_t*)&relh[nb + 8];
            bl_[0] = *(const uint32_t*)&rell[nb];
            bl_[1] = *(const uint32_t*)&rell[nb + 8];
            mma16(qe, qhi[kc], bh_);
            mma16(qe, qhi[kc], bl_);
            mma16(qe, qlo[kc], bh_);
        }
        int col = ni * 8 + 2 * tq;
        if (col < NREL) {
            QEs[(wr + gid) * QEW + col]     = qe[0];
            QEs[(wr + gid + 8) * QEW + col] = qe[2];
        }
        if (col + 1 < NREL) {
            QEs[(wr + gid) * QEW + col + 1]     = qe[1];
            QEs[(wr + gid + 8) * QEW + col + 1] = qe[3];
        }
    }
    __syncthreads();   // rel overlay region now reusable for K/V

    // ---- cp.async setup ----
    const int arow = tid >> 3, ach = (tid & 7) * 8;           // +256: row+32
    const uint32_t dstKV = smb + (arow * 72 + ach) * 2;
    auto issue = [&](int j, int buf) {
        uint32_t bo = buf * AKVB;
        size_t src0 = kvbase + (size_t)(j * 64 + arow) * 64 + ach;
        size_t src1 = src0 + 32 * 64;
        cpa16(dstKV + bo + A_KH, g_KhG + src0);
        cpa16(dstKV + bo + A_KL, g_KlG + src0);
        cpa16(dstKV + bo + A_VH, g_VhG + src0);
        cpa16(dstKV + bo + A_VL, g_VlG + src0);
        uint32_t d2 = dstKV + 32 * 72 * 2;
        cpa16(d2 + bo + A_KH, g_KhG + src1);
        cpa16(d2 + bo + A_KL, g_KlG + src1);
        cpa16(d2 + bo + A_VH, g_VhG + src1);
        cpa16(d2 + bo + A_VL, g_VlG + src1);
    };

    // ldmatrix address bases
    const int lr = lane & 7;
    const uint32_t selK = (lane >= 16) ? (A_KL - A_KH) : 0;
    const uint32_t kbase0 = smb + A_KH + selK + (lr * 72 + ((lane >> 3) & 1) * 8) * 2;
    const uint32_t vbase0 = smb + A_VH + selK + ((((lane >> 3) & 1) * 8 + lr) * 72) * 2;

    float o[8][4];
#pragma unroll
    for (int i = 0; i < 8; i++)
#pragma unroll
        for (int e = 0; e < 4; e++) o[i][e] = 0.f;
    float m0 = -1e30f, m1 = -1e30f, l0 = 0.f, l1 = 0.f;

    issue(0, 0); CP_COMMIT();

    for (int j = 0; j < 32; j++) {
        if (j < 31) { issue(j + 1, (j + 1) & 1); CP_COMMIT(); CP_WAIT(1); }
        else CP_WAIT(0);
        __syncthreads();
        const uint32_t bo = (j & 1) * AKVB;

        // ---- S = Q K^T ----
        float sc[8][4];
#pragma unroll
        for (int ni = 0; ni < 8; ni++)
#pragma unroll
            for (int e = 0; e < 4; e++) sc[ni][e] = 0.f;
#pragma unroll
        for (int kc = 0; kc < 4; kc++) {
#pragma unroll
            for (int ni = 0; ni < 8; ni++) {
                uint32_t kh0, kh1, kl0, kl1;
                ldsm4(kh0, kh1, kl0, kl1,
                      kbase0 + bo + (ni * 8 * 72 + kc * 16) * 2);
                uint32_t bhf[2] = {kh0, kh1}, blf[2] = {kl0, kl1};
                mma16(sc[ni], qhi[kc], bhf);
                mma16(sc[ni], qhi[kc], blf);
                mma16(sc[ni], qlo[kc], bhf);
            }
        }

        // ---- relative-position bias ----
        const int k0 = j * 64;
#pragma unroll
        for (int ni = 0; ni < 8; ni++)
#pragma unroll
            for (int e = 0; e < 4; e++) {
                int ql_ = wr + gid + ((e >> 1) << 3);
                int key = k0 + ni * 8 + (tq << 1) + (e & 1);
                int d2 = (q0 + ql_) - key;
                d2 = d2 < -32 ? -32 : (d2 > 32 ? 32 : d2);
                sc[ni][e] += QEs[ql_ * QEW + d2 + 32];
            }

        // ---- online softmax ----
        float mx0 = -1e30f, mx1 = -1e30f;
#pragma unroll
        for (int ni = 0; ni < 8; ni++) {
            mx0 = fmaxf(mx0, fmaxf(sc[ni][0], sc[ni][1]));
            mx1 = fmaxf(mx1, fmaxf(sc[ni][2], sc[ni][3]));
        }
        mx0 = fmaxf(mx0, __shfl_xor_sync(0xffffffffu, mx0, 1));
        mx0 = fmaxf(mx0, __shfl_xor_sync(0xffffffffu, mx0, 2));
        mx1 = fmaxf(mx1, __shfl_xor_sync(0xffffffffu, mx1, 1));
        mx1 = fmaxf(mx1, __shfl_xor_sync(0xffffffffu, mx1, 2));

        float mn0 = fmaxf(m0, mx0), mn1 = fmaxf(m1, mx1);
        float al0 = __expf(m0 - mn0), al1 = __expf(m1 - mn1);
        float s0 = 0.f, s1 = 0.f;
        uint32_t pAh[8][2], pAl[8][2];
#pragma unroll
        for (int ni = 0; ni < 8; ni++) {
            float p0 = __expf(sc[ni][0] - mn0);
            float p1 = __expf(sc[ni][1] - mn0);
            float p2 = __expf(sc[ni][2] - mn1);
            float p3 = __expf(sc[ni][3] - mn1);
            s0 += p0 + p1;
            s1 += p2 + p3;
            __half h0 = __float2half_rn(p0), h1 = __float2half_rn(p1);
            __half h2 = __float2half_rn(p2), h3 = __float2half_rn(p3);
            pAh[ni][0] = h2u(h0, h1);
            pAh[ni][1] = h2u(h2, h3);
            pAl[ni][0] = h2u(__float2half_rn(p0 - __half2float(h0)),
                             __float2half_rn(p1 - __half2float(h1)));
            pAl[ni][1] = h2u(__float2half_rn(p2 - __half2float(h2)),
                             __float2half_rn(p3 - __half2float(h3)));
        }
        s0 += __shfl_xor_sync(0xffffffffu, s0, 1);
        s0 += __shfl_xor_sync(0xffffffffu, s0, 2);
        s1 += __shfl_xor_sync(0xffffffffu, s1, 1);
        s1 += __shfl_xor_sync(0xffffffffu, s1, 2);
        l0 = l0 * al0 + s0;
        l1 = l1 * al1 + s1;
        m0 = mn0;
        m1 = mn1;
#pragma unroll
        for (int ni = 0; ni < 8; ni++) {
            o[ni][0] *= al0; o[ni][1] *= al0;
            o[ni][2] *= al1; o[ni][3] *= al1;
        }

        // ---- O += P V ----  (A-frags from registers; B via ldmatrix.trans)
#pragma unroll
        for (int kc = 0; kc < 4; kc++) {
            uint32_t ah[4] = {pAh[2 * kc][0], pAh[2 * kc][1],
                              pAh[2 * kc + 1][0], pAh[2 * kc + 1][1]};
            uint32_t alr[4] = {pAl[2 * kc][0], pAl[2 * kc][1],
                               pAl[2 * kc + 1][0], pAl[2 * kc + 1][1]};
#pragma unroll
            for (int ni = 0; ni < 8; ni++) {
                uint32_t vh0, vh1, vl0, vl1;
                ldsm4t(vh0, vh1, vl0, vl1,
                       vbase0 + bo + (kc * 16 * 72 + ni * 8) * 2);
                uint32_t bhf[2] = {vh0, vh1}, blf[2] = {vl0, vl1};
                mma16(o[ni], ah, bhf);
                mma16(o[ni], ah, blf);
                mma16(o[ni], alr, bhf);
            }
        }
        __syncthreads();   // done reading buf before it is refilled
    }

    // ---- normalize + write O (fp32 head layout) ----
    float inv0 = 1.f / l0, inv1 = 1.f / l1;
    float* Og = g_O + ((size_t)bh * S_LEN + q0) * HDIM;
#pragma unroll
    for (int ni = 0; ni < 8; ni++) {
        int col = ni * 8 + (tq << 1);
        *(float2*)(Og + (wr + gid) * HDIM + col) =
            make_float2(o[ni][0] * inv0, o[ni][1] * inv0);
        *(float2*)(Og + (wr + gid + 8) * HDIM + col) =
            make_float2(o[ni][2] * inv1, o[ni][3] * inv1);
    }
}

// =====================================================================
extern "C" void kernel_launch(void* const* d_in, const int* in_sizes, int n_in,
                              void* d_out, int out_size) {
    (void)in_sizes; (void)n_in; (void)out_size;
    const float* x   = (const float*)d_in[0];
    const float* Wq  = (const float*)d_in[1];
    const float* Wk  = (const float*)d_in[2];
    const float* Wv  = (const float*)d_in[3];
    const float* Wo  = (const float*)d_in[4];
    const float* bo  = (const float*)d_in[5];
    const float* rel = (const float*)d_in[6];
    float* out = (float*)d_out;

    conv_k<<<NM * ND / 4 / 256, 256>>>(x,  0, NM * ND, 1.0f);
    conv_k<<<ND * ND / 4 / 256, 256>>>(Wq, 1, ND * ND, 0.125f);   // fold 1/sqrt(64)
    conv_k<<<ND * ND / 4 / 256, 256>>>(Wk, 2, ND * ND, 1.0f);
    conv_k<<<ND * ND / 4 / 256, 256>>>(Wv, 3, ND * ND, 1.0f);
    conv_k<<<ND * ND / 4 / 256, 256>>>(Wo, 4, ND * ND, 1.0f);

    dim3 gg(ND / 128, NM / 128);   // (8, 32)
    gemm_k<0><<<gg, 256>>>(nullptr, nullptr);
    gemm_k<1><<<gg, 256>>>(nullptr, nullptr);
    gemm_k<2><<<gg, 256>>>(nullptr, nullptr);

    cudaFuncSetAttribute((const void*)attn_k,
                         cudaFuncAttributeMaxDynamicSharedMemorySize, ASMEM);
    attn_k<<<dim3(S_LEN / 128, NBH), 256, ASMEM>>>(rel);

    gemm_k<3><<<gg, 256>>>(bo, out);
}

// round 8
// speedup vs baseline: 2.3832x; 1.2463x over previous
#include <cuda_runtime.h>
#include <cuda_fp16.h>
#include <cstdint>

#define S_LEN 2048
#define NHEAD 16
#define HDIM  64
#define NREL  65
#define NBH   32
#define NM    4096
#define ND    1024

// ---------------- static device scratch: hi/lo half planes ----------------
__device__ __half g_xhi[NM * ND],  g_xlo[NM * ND];
__device__ __half g_Whi[4 * ND * ND], g_Wlo[4 * ND * ND];
__device__ __half g_Qh[NBH * S_LEN * HDIM], g_Ql[NBH * S_LEN * HDIM];
__device__ __half g_KhG[NBH * S_LEN * HDIM];
__device__ __half g_VhG[NBH * S_LEN * HDIM];
__device__ __half g_Ohi[NM * ND], g_Olo[NM * ND];

// ---------------- helpers ----------------
__device__ __forceinline__ uint32_t s2u(const void* p) {
    return (uint32_t)__cvta_generic_to_shared(p);
}
__device__ __forceinline__ void cpa16(uint32_t d, const void* s) {
    asm volatile("cp.async.cg.shared.global [%0], [%1], 16;\n" :: "r"(d), "l"(s));
}
#define CP_COMMIT() asm volatile("cp.async.commit_group;\n" ::)
#define CP_WAIT(n)  asm volatile("cp.async.wait_group %0;\n" :: "n"(n))

__device__ __forceinline__ void ldsm4(uint32_t& r0, uint32_t& r1, uint32_t& r2,
                                      uint32_t& r3, uint32_t a) {
    asm volatile("ldmatrix.sync.aligned.m8n8.x4.shared.b16 {%0,%1,%2,%3}, [%4];\n"
                 : "=r"(r0), "=r"(r1), "=r"(r2), "=r"(r3) : "r"(a));
}
__device__ __forceinline__ void ldsm4t(uint32_t& r0, uint32_t& r1, uint32_t& r2,
                                       uint32_t& r3, uint32_t a) {
    asm volatile("ldmatrix.sync.aligned.m8n8.x4.trans.shared.b16 {%0,%1,%2,%3}, [%4];\n"
                 : "=r"(r0), "=r"(r1), "=r"(r2), "=r"(r3) : "r"(a));
}
__device__ __forceinline__ void mma16(float* c, const uint32_t* a, const uint32_t* b) {
    asm volatile(
        "mma.sync.aligned.m16n8k16.row.col.f32.f16.f16.f32 "
        "{%0,%1,%2,%3}, {%4,%5,%6,%7}, {%8,%9}, {%0,%1,%2,%3};\n"
        : "+f"(c[0]), "+f"(c[1]), "+f"(c[2]), "+f"(c[3])
        : "r"(a[0]), "r"(a[1]), "r"(a[2]), "r"(a[3]), "r"(b[0]), "r"(b[1]));
}
__device__ __forceinline__ uint32_t h2u(__half a, __half b) {
    __half2 t = __halves2half2(a, b);
    return *(uint32_t*)&t;
}
__device__ __forceinline__ float ex2(float x) {
    float r;
    asm("ex2.approx.ftz.f32 %0, %1;" : "=f"(r) : "f"(x));
    return r;
}

// ---------------- split-convert kernel ----------------
__global__ void conv_k(const float* __restrict__ in, int which, int n, float scale) {
    int i = (blockIdx.x * blockDim.x + threadIdx.x) << 2;
    if (i >= n) return;
    __half *hi, *lo;
    if (which == 0) { hi = g_xhi; lo = g_xlo; }
    else { hi = g_Whi + (size_t)(which - 1) * ND * ND; lo = g_Wlo + (size_t)(which - 1) * ND * ND; }
    float4 v = *(const float4*)(in + i);
    float f0 = v.x * scale, f1 = v.y * scale, f2 = v.z * scale, f3 = v.w * scale;
    __half h0 = __float2half_rn(f0), h1 = __float2half_rn(f1);
    __half h2 = __float2half_rn(f2), h3 = __float2half_rn(f3);
    *(__half2*)&hi[i]     = __halves2half2(h0, h1);
    *(__half2*)&hi[i + 2] = __halves2half2(h2, h3);
    *(__half2*)&lo[i]     = __halves2half2(__float2half_rn(f0 - __half2float(h0)),
                                           __float2half_rn(f1 - __half2float(h1)));
    *(__half2*)&lo[i + 2] = __halves2half2(__float2half_rn(f2 - __half2float(h2)),
                                           __float2half_rn(f3 - __half2float(h3)));
}

// =====================================================================
// GEMM: C[m,n] = sum_k A[m,k] * W[n,k], fp16-split 3-term, cp.async + ldmatrix
// MODE 0: -> Q hi/lo planes. MODE 1/2: -> K/V hi plane only.
// MODE 3: A = O planes -> fp32 d_out + bias
// =====================================================================
#define SAH 24
#define GPLANE 3072
#define GBUFB 24576

template <int MODE>
__global__ __launch_bounds__(256) void gemm_k(const float* __restrict__ bias,
                                              float* __restrict__ Cout) {
    __shared__ __align__(16) __half sm[2 * 4 * GPLANE];   // 48KB

    const int tid = threadIdx.x, lane = tid & 31, wrp = tid >> 5;
    const int gid = lane >> 2, tq = lane & 3;
    const int wm = (wrp >> 2) * 64, wn = (wrp & 3) * 32;
    const int m0 = blockIdx.y * 128, n0 = blockIdx.x * 128;
    const uint32_t smb = s2u(sm);

    const int wsel = (MODE == 3) ? 3 : MODE;
    const __half* Wh = g_Whi + (size_t)wsel * ND * ND;
    const __half* Wl = g_Wlo + (size_t)wsel * ND * ND;
    const __half* Ah = (MODE == 3) ? g_Ohi : g_xhi;
    const __half* Al = (MODE == 3) ? g_Olo : g_xlo;

    const int lb = lane >> 3, lr = lane & 7;
    const uint32_t addrA0 = smb + ((wm + (lb & 1) * 8 + lr) * SAH + (lb >> 1) * 8) * 2;
    const uint32_t addrB0 = smb + 2 * GPLANE * 2 +
                            ((wn + (lane >> 4) * 8 + lr) * SAH + ((lane >> 3) & 1) * 8) * 2;

    const int rowc = tid >> 1, chc = (tid & 1) * 8;
    const uint32_t dA = smb + (rowc * SAH + chc) * 2;
    const uint32_t dB = smb + 2 * GPLANE * 2 + (rowc * SAH + chc) * 2;
    const __half* srcAh = Ah + (size_t)(m0 + rowc) * ND + chc;
    const __half* srcAl = Al + (size_t)(m0 + rowc) * ND + chc;
    const __half* srcBh = Wh + (size_t)(n0 + rowc) * ND + chc;
    const __half* srcBl = Wl + (size_t)(n0 + rowc) * ND + chc;

    float acc[4][4][4];
#pragma unroll
    for (int i = 0; i < 4; i++)
#pragma unroll
        for (int j = 0; j < 4; j++)
#pragma unroll
            for (int e = 0; e < 4; e++) acc[i][j][e] = 0.f;

    auto issueAsync = [&](int kc, int buf) {
        uint32_t bo = buf * GBUFB;
        cpa16(dA + bo,              srcAh + kc);
        cpa16(dA + bo + GPLANE * 2, srcAl + kc);
        cpa16(dB + bo,              srcBh + kc);
        cpa16(dB + bo + GPLANE * 2, srcBl + kc);
    };

    auto compute = [&](int buf) {
        uint32_t bo = buf * GBUFB;
        uint32_t ah[4][4], al[4][4];
#pragma unroll
        for (int mi = 0; mi < 4; mi++) {
            ldsm4(ah[mi][0], ah[mi][1], ah[mi][2], ah[mi][3],
                  addrA0 + bo + mi * 16 * SAH * 2);
            ldsm4(al[mi][0], al[mi][1], al[mi][2], al[mi][3],
                  addrA0 + bo + GPLANE * 2 + mi * 16 * SAH * 2);
        }
        uint32_t bh[4][2], bl[4][2];
#pragma unroll
        for (int p = 0; p < 2; p++) {
            ldsm4(bh[2 * p][0], bh[2 * p][1], bh[2 * p + 1][0], bh[2 * p + 1][1],
                  addrB0 + bo + p * 16 * SAH * 2);
            ldsm4(bl[2 * p][0], bl[2 * p][1], bl[2 * p + 1][0], bl[2 * p + 1][1],
                  addrB0 + bo + GPLANE * 2 + p * 16 * SAH * 2);
        }
#pragma unroll
        for (int ni = 0; ni < 4; ni++)
#pragma unroll
            for (int mi = 0; mi < 4; mi++) {
                mma16(acc[mi][ni], ah[mi], bh[ni]);
                mma16(acc[mi][ni], ah[mi], bl[ni]);
                mma16(acc[mi][ni], al[mi], bh[ni]);
            }
    };

    issueAsync(0, 0); CP_COMMIT();
    for (int c = 0; c < 64; c++) {
        if (c < 63) { issueAsync((c + 1) << 4, (c + 1) & 1); CP_COMMIT(); CP_WAIT(1); }
        else CP_WAIT(0);
        __syncthreads();
        compute(c & 1);
        __syncthreads();
    }

    // epilogue
#pragma unroll
    for (int mi = 0; mi < 4; mi++)
#pragma unroll
        for (int ni = 0; ni < 4; ni++)
#pragma unroll
            for (int half_ = 0; half_ < 2; half_++) {
                int row = m0 + wm + mi * 16 + gid + half_ * 8;
                int col = n0 + wn + ni * 8 + tq * 2;
                float v0 = acc[mi][ni][half_ * 2];
                float v1 = acc[mi][ni][half_ * 2 + 1];
                if (MODE == 3) {
                    v0 += bias[col];
                    v1 += bias[col + 1];
                    *(float2*)(Cout + (size_t)row * ND + col) = make_float2(v0, v1);
                } else {
                    int b = row >> 11, s = row & 2047, h = col >> 6, d = col & 63;
                    size_t idx = (((size_t)(b * NHEAD + h)) * S_LEN + s) * HDIM + d;
                    __half h0 = __float2half_rn(v0), h1 = __float2half_rn(v1);
                    if (MODE == 0) {
                        *(__half2*)&g_Qh[idx] = __halves2half2(h0, h1);
                        *(__half2*)&g_Ql[idx] = __halves2half2(
                            __float2half_rn(v0 - __half2float(h0)),
                            __float2half_rn(v1 - __half2float(h1)));
                    } else {
                        __half* dh = (MODE == 1) ? g_KhG : g_VhG;
                        *(__half2*)&dh[idx] = __halves2half2(h0, h1);
                    }
                }
            }
}

// =====================================================================
// Flash attention: S = Q_full * K_hi (2-term), PV = P_hi * V_hi (1-term).
// K/V single hi planes; log2-domain softmax (ex2). 128 q rows, 8 warps.
// =====================================================================
#define AKVB 18432            // per buffer: K_h + V_h (64x72 halves each)
#define A_KH 0
#define A_VH 9216
#define QEW  66
#define ASMEM (2 * AKVB + 128 * QEW * 4)   // 36864 + 33792 = 70656

__global__ __launch_bounds__(256) void attn_k(const float* __restrict__ rel) {
    extern __shared__ char smraw[];
    float* QEs = (float*)(smraw + 2 * AKVB);
    __half* relh = (__half*)smraw;            // prologue overlay (72x72 x2 planes)
    __half* rell = relh + 72 * 72;
    const uint32_t smb = s2u(smraw);

    const int tid = threadIdx.x, lane = tid & 31, w = tid >> 5;
    const int gid = lane >> 2, tq = lane & 3, wr = w * 16;
    const int q0 = blockIdx.x * 128;
    const int bh = blockIdx.y;
    const size_t kvbase = (size_t)bh * S_LEN * HDIM;

    // rel staged x8 (counters Wq's 1/8; log2e factor arrives via Q)
    for (int i = tid; i < 72 * 64; i += 256) {
        int v = i >> 6, d = i & 63;
        float rv = (v < NREL) ? rel[v * 64 + d] * 8.0f : 0.f;
        __half h = __float2half_rn(rv);
        relh[v * 72 + d] = h;
        rell[v * 72 + d] = __float2half_rn(rv - __half2float(h));
    }

    // Q fragments (carry 0.125*log2e from Wq pre-scaling)
    uint32_t qhi[4][4], qlo[4][4];
    {
        const size_t qb = ((size_t)bh * S_LEN + q0) * HDIM;
        const __half* qh = g_Qh + qb;
        const __half* ql = g_Ql + qb;
#pragma unroll
        for (int kc = 0; kc < 4; kc++) {
            int c0 = kc * 16 + 2 * tq;
            size_t r0 = (size_t)(wr + gid) * 64, r1 = (size_t)(wr + gid + 8) * 64;
            qhi[kc][0] = *(const uint32_t*)(qh + r0 + c0);
            qhi[kc][1] = *(const uint32_t*)(qh + r1 + c0);
            qhi[kc][2] = *(const uint32_t*)(qh + r0 + c0 + 8);
            qhi[kc][3] = *(const uint32_t*)(qh + r1 + c0 + 8);
            qlo[kc][0] = *(const uint32_t*)(ql + r0 + c0);
            qlo[kc][1] = *(const uint32_t*)(ql + r1 + c0);
            qlo[kc][2] = *(const uint32_t*)(ql + r0 + c0 + 8);
            qlo[kc][3] = *(const uint32_t*)(ql + r1 + c0 + 8);
        }
    }
    __syncthreads();

    // qe = Q . rel^T (log2-domain result; 3-term, negligible cost)
#pragma unroll
    for (int ni = 0; ni < 9; ni++) {
        float qe[4] = {0.f, 0.f, 0.f, 0.f};
#pragma unroll
        for (int kc = 0; kc < 4; kc++) {
            int nb = (ni * 8 + gid) * 72 + kc * 16 + 2 * tq;
            uint32_t bh_[2], bl_[2];
            bh_[0] = *(const uint32_t*)&relh[nb];
            bh_[1] = *(const uint32_t*)&relh[nb + 8];
            bl_[0] = *(const uint32_t*)&rell[nb];
            bl_[1] = *(const uint32_t*)&rell[nb + 8];
            mma16(qe, qhi[kc], bh_);
            mma16(qe, qhi[kc], bl_);
            mma16(qe, qlo[kc], bh_);
        }
        int col = ni * 8 + 2 * tq;
        if (col < NREL) {
            QEs[(wr + gid) * QEW + col]     = qe[0];
            QEs[(wr + gid + 8) * QEW + col] = qe[2];
        }
        if (col + 1 < NREL) {
            QEs[(wr + gid) * QEW + col + 1]     = qe[1];
            QEs[(wr + gid + 8) * QEW + col + 1] = qe[3];
        }
    }
    __syncthreads();   // rel overlay region reusable for K/V

    // cp.async: 2 planes, 64 rows each (two 32-row sets per thread)
    const int arow = tid >> 3, ach = (tid & 7) * 8;
    const uint32_t dstKV = smb + (arow * 72 + ach) * 2;
    auto issue = [&](int j, int buf) {
        uint32_t bo = buf * AKVB;
        size_t src0 = kvbase + (size_t)(j * 64 + arow) * 64 + ach;
        size_t src1 = src0 + 32 * 64;
        cpa16(dstKV + bo + A_KH, g_KhG + src0);
        cpa16(dstKV + bo + A_VH, g_VhG + src0);
        uint32_t d2 = dstKV + 32 * 72 * 2;
        cpa16(d2 + bo + A_KH, g_KhG + src1);
        cpa16(d2 + bo + A_VH, g_VhG + src1);
    };

    // ldmatrix bases: one x4 fetches two k16 fragments
    const int lr = lane & 7;
    // K: row = ni*8+lr, col = kcp*32 + (lane>>3)*8
    const uint32_t kbase0 = smb + A_KH + (lr * 72 + (lane >> 3) * 8) * 2;
    // V (trans): row = kcp*32 + (lane>>3)*8 + lr, col = ni*8
    const uint32_t vbase0 = smb + A_VH + (((lane >> 3) * 8 + lr) * 72) * 2;

    float o[8][4];
#pragma unroll
    for (int i = 0; i < 8; i++)
#pragma unroll
        for (int e = 0; e < 4; e++) o[i][e] = 0.f;
    float m0 = -1e30f, m1 = -1e30f, l0 = 0.f, l1 = 0.f;

    issue(0, 0); CP_COMMIT();

    for (int j = 0; j < 32; j++) {
        if (j < 31) { issue(j + 1, (j + 1) & 1); CP_COMMIT(); CP_WAIT(1); }
        else CP_WAIT(0);
        __syncthreads();
        const uint32_t bo = (j & 1) * AKVB;

        // ---- S = Q K_hi^T (2-term) ----
        float sc[8][4];
#pragma unroll
        for (int ni = 0; ni < 8; ni++)
#pragma unroll
            for (int e = 0; e < 4; e++) sc[ni][e] = 0.f;
#pragma unroll
        for (int ni = 0; ni < 8; ni++) {
#pragma unroll
            for (int kcp = 0; kcp < 2; kcp++) {
                uint32_t k0r, k1r, k2r, k3r;
                ldsm4(k0r, k1r, k2r, k3r,
                      kbase0 + bo + (ni * 576 + kcp * 32) * 2);
                uint32_t f01[2] = {k0r, k1r}, f23[2] = {k2r, k3r};
                mma16(sc[ni], qhi[2 * kcp], f01);
                mma16(sc[ni], qlo[2 * kcp], f01);
                mma16(sc[ni], qhi[2 * kcp + 1], f23);
                mma16(sc[ni], qlo[2 * kcp + 1], f23);
            }
        }

        // ---- relative-position bias (log2 domain) ----
        const int k0 = j * 64;
#pragma unroll
        for (int ni = 0; ni < 8; ni++)
#pragma unroll
            for (int e = 0; e < 4; e++) {
                int ql_ = wr + gid + ((e >> 1) << 3);
                int key = k0 + ni * 8 + (tq << 1) + (e & 1);
                int d2 = (q0 + ql_) - key;
                d2 = d2 < -32 ? -32 : (d2 > 32 ? 32 : d2);
                sc[ni][e] += QEs[ql_ * QEW + d2 + 32];
            }

        // ---- online softmax (base-2) ----
        float mx0 = -1e30f, mx1 = -1e30f;
#pragma unroll
        for (int ni = 0; ni < 8; ni++) {
            mx0 = fmaxf(mx0, fmaxf(sc[ni][0], sc[ni][1]));
            mx1 = fmaxf(mx1, fmaxf(sc[ni][2], sc[ni][3]));
        }
        mx0 = fmaxf(mx0, __shfl_xor_sync(0xffffffffu, mx0, 1));
        mx0 = fmaxf(mx0, __shfl_xor_sync(0xffffffffu, mx0, 2));
        mx1 = fmaxf(mx1, __shfl_xor_sync(0xffffffffu, mx1, 1));
        mx1 = fmaxf(mx1, __shfl_xor_sync(0xffffffffu, mx1, 2));

        float mn0 = fmaxf(m0, mx0), mn1 = fmaxf(m1, mx1);
        float al0 = ex2(m0 - mn0), al1 = ex2(m1 - mn1);
        float s0 = 0.f, s1 = 0.f;
        uint32_t pAh[8][2];
#pragma unroll
        for (int ni = 0; ni < 8; ni++) {
            float p0 = ex2(sc[ni][0] - mn0);
            float p1 = ex2(sc[ni][1] - mn0);
            float p2 = ex2(sc[ni][2] - mn1);
            float p3 = ex2(sc[ni][3] - mn1);
            s0 += p0 + p1;
            s1 += p2 + p3;
            pAh[ni][0] = h2u(__float2half_rn(p0), __float2half_rn(p1));
            pAh[ni][1] = h2u(__float2half_rn(p2), __float2half_rn(p3));
        }
        s0 += __shfl_xor_sync(0xffffffffu, s0, 1);
        s0 += __shfl_xor_sync(0xffffffffu, s0, 2);
        s1 += __shfl_xor_sync(0xffffffffu, s1, 1);
        s1 += __shfl_xor_sync(0xffffffffu, s1, 2);
        l0 = l0 * al0 + s0;
        l1 = l1 * al1 + s1;
        m0 = mn0;
        m1 = mn1;
#pragma unroll
        for (int ni = 0; ni < 8; ni++) {
            o[ni][0] *= al0; o[ni][1] *= al0;
            o[ni][2] *= al1; o[ni][3] *= al1;
        }

        // ---- O += P_hi V_hi (1-term) ----
#pragma unroll
        for (int kcp = 0; kcp < 2; kcp++) {
            uint32_t a0[4] = {pAh[4 * kcp][0],     pAh[4 * kcp][1],
                              pAh[4 * kcp + 1][0], pAh[4 * kcp + 1][1]};
            uint32_t a1[4] = {pAh[4 * kcp + 2][0], pAh[4 * kcp + 2][1],
                              pAh[4 * kcp + 3][0], pAh[4 * kcp + 3][1]};
#pragma unroll
            for (int ni = 0; ni < 8; ni++) {
                uint32_t v0r, v1r, v2r, v3r;
                ldsm4t(v0r, v1r, v2r, v3r,
                       vbase0 + bo + (kcp * 2304 + ni * 8) * 2);
                uint32_t f01[2] = {v0r, v1r}, f23[2] = {v2r, v3r};
                mma16(o[ni], a0, f01);
                mma16(o[ni], a1, f23);
            }
        }
        __syncthreads();
    }

    // ---- normalize + write O as row-major hi/lo planes ----
    float inv0 = 1.f / l0, inv1 = 1.f / l1;
    const int rowg = (bh >> 4) * S_LEN + q0;
    const int colh = (bh & 15) * 64;
#pragma unroll
    for (int ni = 0; ni < 8; ni++) {
        int col = colh + ni * 8 + (tq << 1);
        size_t r0 = (size_t)(rowg + wr + gid) * ND + col;
        size_t r1 = (size_t)(rowg + wr + gid + 8) * ND + col;
        float v0 = o[ni][0] * inv0, v1 = o[ni][1] * inv0;
        __half h0 = __float2half_rn(v0), h1 = __float2half_rn(v1);
        *(__half2*)&g_Ohi[r0] = __halves2half2(h0, h1);
        *(__half2*)&g_Olo[r0] = __halves2half2(__float2half_rn(v0 - __half2float(h0)),
                                               __float2half_rn(v1 - __half2float(h1)));
        float v2 = o[ni][2] * inv1, v3 = o[ni][3] * inv1;
        __half h2 = __float2half_rn(v2), h3 = __float2half_rn(v3);
        *(__half2*)&g_Ohi[r1] = __halves2half2(h2, h3);
        *(__half2*)&g_Olo[r1] = __halves2half2(__float2half_rn(v2 - __half2float(h2)),
                                               __float2half_rn(v3 - __half2float(h3)));
    }
}

// =====================================================================
extern "C" void kernel_launch(void* const* d_in, const int* in_sizes, int n_in,
                              void* d_out, int out_size) {
    (void)in_sizes; (void)n_in; (void)out_size;
    const float* x   = (const float*)d_in[0];
    const float* Wq  = (const float*)d_in[1];
    const float* Wk  = (const float*)d_in[2];
    const float* Wv  = (const float*)d_in[3];
    const float* Wo  = (const float*)d_in[4];
    const float* bo  = (const float*)d_in[5];
    const float* rel = (const float*)d_in[6];
    float* out = (float*)d_out;

    // Wq carries attn scale (1/8) * log2(e) so softmax runs in base-2
    conv_k<<<NM * ND / 4 / 256, 256>>>(x,  0, NM * ND, 1.0f);
    conv_k<<<ND * ND / 4 / 256, 256>>>(Wq, 1, ND * ND, 0.125f * 1.44269504088896f);
    conv_k<<<ND * ND / 4 / 256, 256>>>(Wk, 2, ND * ND, 1.0f);
    conv_k<<<ND * ND / 4 / 256, 256>>>(Wv, 3, ND * ND, 1.0f);
    conv_k<<<ND * ND / 4 / 256, 256>>>(Wo, 4, ND * ND, 1.0f);

    dim3 gg(ND / 128, NM / 128);   // (8, 32)
    gemm_k<0><<<gg, 256>>>(nullptr, nullptr);
    gemm_k<1><<<gg, 256>>>(nullptr, nullptr);
    gemm_k<2><<<gg, 256>>>(nullptr, nullptr);

    cudaFuncSetAttribute((const void*)attn_k,
                         cudaFuncAttributeMaxDynamicSharedMemorySize, ASMEM);
    attn_k<<<dim3(S_LEN / 128, NBH), 256, ASMEM>>>(rel);

    gemm_k<3><<<gg, 256>>>(bo, out);
}